// round 1
// baseline (speedup 1.0000x reference)
#include <cuda_runtime.h>

// Problem constants
#define NN   3072
#define FF   256
#define HH   8
#define DD   128
#define OUTD 64
#define MAXD 384   // max degree capacity (mean 153.6, sd 12 -> 384 is >18 sigma)

// ---------------- device scratch (no allocations allowed) ----------------
__device__ float g_h  [NN * FF];        // merged state
__device__ float g_Wh [HH * NN * DD];   // per-head Wh (layer0, then layer1)
__device__ float g_ha [HH * NN * DD];   // per-head hidden (h0, then h1)
__device__ float g_hc [NN * HH * DD];   // concatenated heads
__device__ float g_who[NN * OUTD];      // output-layer Wh
__device__ float g_f1 [HH * NN];
__device__ float g_f2 [HH * NN];
__device__ float g_f1o[NN];
__device__ float g_f2o[NN];
__device__ int   g_nbr[NN * MAXD];
__device__ int   g_deg[NN];

// ---------------- prep: h = x + (obs==1) * theta ----------------
__global__ void prep_kernel(const float* __restrict__ x,
                            const int* __restrict__ obs,
                            const float* __restrict__ theta) {
    int idx = blockIdx.x * blockDim.x + threadIdx.x;
    if (idx >= NN * FF) return;
    int i = idx / FF;
    int t = idx - i * FF;
    float add = (obs[i] == 1) ? theta[t] : 0.0f;
    g_h[idx] = x[idx] + add;
}

// ---------------- CSR build from dense adjacency ----------------
__global__ void build_csr_kernel(const float* __restrict__ adj) {
    int i = blockIdx.x;
    __shared__ int cnt;
    if (threadIdx.x == 0) cnt = 0;
    __syncthreads();
    const float* row = adj + (long)i * NN;
    for (int j = threadIdx.x; j < NN; j += blockDim.x) {
        if (row[j] > 0.0f) {
            int p = atomicAdd(&cnt, 1);
            if (p < MAXD) g_nbr[i * MAXD + p] = j;
        }
    }
    __syncthreads();
    if (threadIdx.x == 0) g_deg[i] = cnt < MAXD ? cnt : MAXD;
}

// ---------------- tiled SGEMM: C[M,Nc] = A[M,K] @ B[K,Nc], batched over z ----------------
template <int BM, int BN, int BK, int TM, int TN>
__global__ void sgemm_kernel(const float* __restrict__ A,
                             const float* __restrict__ B,
                             float* __restrict__ C,
                             int M, int Nc, int K,
                             long strideA, long strideB, long strideC) {
    constexpr int THREADS = (BM / TM) * (BN / TN);
    int z = blockIdx.z;
    A += (long)z * strideA;
    B += (long)z * strideB;
    C += (long)z * strideC;

    __shared__ float As[BK][BM];
    __shared__ float Bs[BK][BN];

    int brow = blockIdx.y * BM;
    int bcol = blockIdx.x * BN;
    int tid  = threadIdx.x;
    int tcol = tid % (BN / TN);
    int trow = tid / (BN / TN);

    float acc[TM][TN];
#pragma unroll
    for (int i = 0; i < TM; i++)
#pragma unroll
        for (int j = 0; j < TN; j++) acc[i][j] = 0.0f;

    for (int k0 = 0; k0 < K; k0 += BK) {
        // load A tile (BM x BK) as float4 along K, store transposed
        constexpr int A_LOADS = (BM * BK) / (4 * THREADS);
#pragma unroll
        for (int l = 0; l < A_LOADS; l++) {
            int idx = tid + l * THREADS;        // over BM * (BK/4)
            int r  = idx / (BK / 4);
            int c4 = idx % (BK / 4);
            float4 v = *(const float4*)&A[(long)(brow + r) * K + k0 + c4 * 4];
            As[c4 * 4 + 0][r] = v.x;
            As[c4 * 4 + 1][r] = v.y;
            As[c4 * 4 + 2][r] = v.z;
            As[c4 * 4 + 3][r] = v.w;
        }
        // load B tile (BK x BN) as float4 along N
        constexpr int B_LOADS = (BK * BN) / (4 * THREADS);
#pragma unroll
        for (int l = 0; l < B_LOADS; l++) {
            int idx = tid + l * THREADS;        // over BK * (BN/4)
            int r  = idx / (BN / 4);
            int c4 = idx % (BN / 4);
            float4 v = *(const float4*)&B[(long)(k0 + r) * Nc + bcol + c4 * 4];
            *(float4*)&Bs[r][c4 * 4] = v;
        }
        __syncthreads();
#pragma unroll
        for (int kk = 0; kk < BK; kk++) {
            float a[TM], b[TN];
#pragma unroll
            for (int i = 0; i < TM; i++) a[i] = As[kk][trow * TM + i];
#pragma unroll
            for (int j = 0; j < TN; j++) b[j] = Bs[kk][tcol * TN + j];
#pragma unroll
            for (int i = 0; i < TM; i++)
#pragma unroll
                for (int j = 0; j < TN; j++) acc[i][j] += a[i] * b[j];
        }
        __syncthreads();
    }
#pragma unroll
    for (int i = 0; i < TM; i++) {
        int r = brow + trow * TM + i;
#pragma unroll
        for (int j = 0; j < TN; j++) {
            C[(long)r * Nc + bcol + tcol * TN + j] = acc[i][j];
        }
    }
}

// ---------------- f1/f2 = Wh @ a (one warp per (head,row)) ----------------
__global__ void fvec_kernel(const float* __restrict__ Wh,
                            const float* __restrict__ a,
                            float* __restrict__ f1,
                            float* __restrict__ f2,
                            int D, int totalRows) {
    int gw   = (blockIdx.x * blockDim.x + threadIdx.x) >> 5;
    int lane = threadIdx.x & 31;
    if (gw >= totalRows) return;
    int h = gw / NN;
    int i = gw - h * NN;
    const float* w  = Wh + ((long)h * NN + i) * D;
    const float* av = a + (long)h * 2 * D;
    float s1 = 0.0f, s2 = 0.0f;
    for (int t = lane; t < D; t += 32) {
        float v = w[t];
        s1 += v * av[t];
        s2 += v * av[D + t];
    }
#pragma unroll
    for (int o = 16; o; o >>= 1) {
        s1 += __shfl_down_sync(0xffffffffu, s1, o);
        s2 += __shfl_down_sync(0xffffffffu, s2, o);
    }
    if (lane == 0) {
        f1[h * NN + i] = s1;
        f2[h * NN + i] = s2;
    }
}

// ---------------- block reductions ----------------
template <int BLOCK>
__device__ __forceinline__ float block_reduce(float v, float* red, bool isMax) {
    const unsigned FULL = 0xffffffffu;
#pragma unroll
    for (int o = 16; o; o >>= 1) {
        float t = __shfl_down_sync(FULL, v, o);
        v = isMax ? fmaxf(v, t) : (v + t);
    }
    int lane = threadIdx.x & 31;
    int wid  = threadIdx.x >> 5;
    constexpr int NW = BLOCK / 32;
    if (lane == 0) red[wid] = v;
    __syncthreads();
    if (wid == 0) {
        float r = (lane < NW) ? red[lane] : (isMax ? -3.4e38f : 0.0f);
#pragma unroll
        for (int o = 16; o; o >>= 1) {
            float t = __shfl_down_sync(FULL, r, o);
            r = isMax ? fmaxf(r, t) : (r + t);
        }
        if (lane == 0) red[0] = r;
    }
    __syncthreads();
    float result = red[0];
    __syncthreads();   // protect red before reuse
    return result;
}

// ---------------- fused sparse attention + ELU ----------------
// grid = (NN, nHeads), block = D threads. out[(h*NN+i)*D + t]
template <int D, int BLOCK>
__global__ void attn_kernel(const float* __restrict__ Wh,
                            const float* __restrict__ f1,
                            const float* __restrict__ f2,
                            float* __restrict__ out) {
    int i = blockIdx.x;
    int h = blockIdx.y;
    const float* WhH = Wh + (long)h * NN * D;
    const float* f2H = f2 + (long)h * NN;
    float f1i = f1[(long)h * NN + i];

    __shared__ float w[MAXD];
    __shared__ int   nb[MAXD];
    __shared__ float red[BLOCK / 32];

    int d   = g_deg[i];
    int tid = threadIdx.x;

    // phase 1: e_j = leakyrelu(f1_i + f2_j) for neighbors
    for (int k = tid; k < d; k += BLOCK) {
        int j = g_nbr[i * MAXD + k];
        nb[k] = j;
        float e = f1i + f2H[j];
        w[k] = (e > 0.0f) ? e : 0.2f * e;
    }
    __syncthreads();

    float m = -3.4e38f;
    for (int k = tid; k < d; k += BLOCK) m = fmaxf(m, w[k]);
    m = block_reduce<BLOCK>(m, red, true);

    float s = 0.0f;
    for (int k = tid; k < d; k += BLOCK) {
        float v = expf(w[k] - m);
        w[k] = v;
        s += v;
    }
    s = block_reduce<BLOCK>(s, red, false);   // includes barrier: w[] visible after

    float acc = 0.0f;
    if (d > 0) {
        float inv = 1.0f / s;
#pragma unroll 4
        for (int k = 0; k < d; k++) {
            acc += w[k] * WhH[(long)nb[k] * D + tid];
        }
        acc *= inv;
    } else {
        // uniform attention over all nodes (softmax of constant row)
        for (int j = 0; j < NN; j++) acc += WhH[(long)j * D + tid];
        acc *= (1.0f / NN);
    }
    // ELU
    float r = (acc > 0.0f) ? acc : expm1f(acc);
    out[((long)h * NN + i) * D + tid] = r;
}

// ---------------- concat heads: hc[i, h*DD + t] = ha[h][i][t] ----------------
__global__ void pack_kernel(const float* __restrict__ src, float* __restrict__ dst) {
    long idx = (long)blockIdx.x * blockDim.x + threadIdx.x;
    if (idx >= (long)NN * HH * DD) return;
    int t = idx % DD;
    long r = idx / DD;
    int h = r % HH;
    long i = r / HH;
    dst[idx] = src[((long)h * NN + i) * DD + t];
}

// ---------------- launch ----------------
extern "C" void kernel_launch(void* const* d_in, const int* in_sizes, int n_in,
                              void* d_out, int out_size) {
    const float* x     = (const float*)d_in[0];
    const float* adj   = (const float*)d_in[1];
    const int*   obs   = (const int*)  d_in[2];
    // d_in[3] = s_mat (unused)
    const float* theta = (const float*)d_in[4];
    const float* W0    = (const float*)d_in[5];
    const float* a0    = (const float*)d_in[6];
    const float* W1    = (const float*)d_in[7];
    const float* a1    = (const float*)d_in[8];
    const float* Wo    = (const float*)d_in[9];
    const float* ao    = (const float*)d_in[10];
    float* out = (float*)d_out;

    void *pH, *pWh, *pHa, *pHc, *pWho, *pF1, *pF2, *pF1o, *pF2o;
    cudaGetSymbolAddress(&pH,   g_h);
    cudaGetSymbolAddress(&pWh,  g_Wh);
    cudaGetSymbolAddress(&pHa,  g_ha);
    cudaGetSymbolAddress(&pHc,  g_hc);
    cudaGetSymbolAddress(&pWho, g_who);
    cudaGetSymbolAddress(&pF1,  g_f1);
    cudaGetSymbolAddress(&pF2,  g_f2);
    cudaGetSymbolAddress(&pF1o, g_f1o);
    cudaGetSymbolAddress(&pF2o, g_f2o);

    // 1. merge state
    prep_kernel<<<(NN * FF + 255) / 256, 256>>>(x, obs, theta);
    // 2. adjacency -> CSR
    build_csr_kernel<<<NN, 256>>>(adj);

    // ---- layer 0 ----
    sgemm_kernel<128, 128, 16, 8, 8><<<dim3(1, NN / 128, HH), 256>>>(
        (const float*)pH, W0, (float*)pWh, NN, DD, FF,
        0L, (long)FF * DD, (long)NN * DD);
    fvec_kernel<<<(HH * NN) / 8, 256>>>((const float*)pWh, a0,
                                        (float*)pF1, (float*)pF2, DD, HH * NN);
    attn_kernel<DD, DD><<<dim3(NN, HH), DD>>>((const float*)pWh,
                                              (const float*)pF1, (const float*)pF2,
                                              (float*)pHa);

    // ---- layer 1 ----
    sgemm_kernel<128, 128, 16, 8, 8><<<dim3(1, NN / 128, HH), 256>>>(
        (const float*)pHa, W1, (float*)pWh, NN, DD, DD,
        (long)NN * DD, (long)DD * DD, (long)NN * DD);
    fvec_kernel<<<(HH * NN) / 8, 256>>>((const float*)pWh, a1,
                                        (float*)pF1, (float*)pF2, DD, HH * NN);
    attn_kernel<DD, DD><<<dim3(NN, HH), DD>>>((const float*)pWh,
                                              (const float*)pF1, (const float*)pF2,
                                              (float*)pHa);

    // ---- concat + output layer ----
    pack_kernel<<<(int)(((long)NN * HH * DD + 255) / 256), 256>>>(
        (const float*)pHa, (float*)pHc);
    sgemm_kernel<128, 64, 16, 8, 4><<<dim3(1, NN / 128, 1), 256>>>(
        (const float*)pHc, Wo, (float*)pWho, NN, OUTD, HH * DD,
        0L, 0L, 0L);
    fvec_kernel<<<(NN + 7) / 8, 256>>>((const float*)pWho, ao,
                                       (float*)pF1o, (float*)pF2o, OUTD, NN);
    attn_kernel<OUTD, OUTD><<<dim3(NN, 1), OUTD>>>((const float*)pWho,
                                                   (const float*)pF1o, (const float*)pF2o,
                                                   out);
    (void)in_sizes; (void)n_in; (void)out_size;
}

// round 2
// speedup vs baseline: 1.4359x; 1.4359x over previous
#include <cuda_runtime.h>
#include <cuda_bf16.h>

// Problem constants
#define NN   3072
#define FF   256
#define HH   8
#define DD   128
#define OUTD 64
#define MAXD 384   // degree ~ Binom(3072,0.05): mean 153.6, sd 12 -> 384 is huge margin

// ---------------- device scratch (no allocations allowed) ----------------
__device__ __align__(16) float         g_h   [NN * FF];        // merged state
__device__ __align__(16) __nv_bfloat16 g_Whb [HH * NN * DD];   // per-head Wh (bf16, gather operand)
__device__ __align__(16) float         g_ha  [HH * NN * DD];   // layer-0 attention output (fp32)
__device__ __align__(16) float         g_hc  [NN * HH * DD];   // layer-1 attn output, packed concat
__device__ __align__(16) __nv_bfloat16 g_Whob[NN * OUTD];      // output-layer Wh (bf16)
__device__ float g_f1 [HH * NN];
__device__ float g_f2 [HH * NN];
__device__ float g_f1o[NN];
__device__ float g_f2o[NN];
__device__ int   g_nbr[NN * MAXD];
__device__ int   g_deg[NN];

// ---------------- prep: h = x + (obs==1) * theta ----------------
__global__ void prep_kernel(const float* __restrict__ x,
                            const int* __restrict__ obs,
                            const float* __restrict__ theta) {
    int idx = blockIdx.x * blockDim.x + threadIdx.x;
    if (idx >= NN * FF) return;
    int i = idx / FF;
    int t = idx - i * FF;
    float add = (obs[i] == 1) ? theta[t] : 0.0f;
    g_h[idx] = x[idx] + add;
}

// ---------------- CSR build from dense adjacency ----------------
__global__ void build_csr_kernel(const float* __restrict__ adj) {
    int i = blockIdx.x;
    __shared__ int cnt;
    if (threadIdx.x == 0) cnt = 0;
    __syncthreads();
    const float* row = adj + (long)i * NN;
    for (int j = threadIdx.x; j < NN; j += blockDim.x) {
        if (row[j] > 0.0f) {
            int p = atomicAdd(&cnt, 1);
            if (p < MAXD) g_nbr[i * MAXD + p] = j;
        }
    }
    __syncthreads();
    if (threadIdx.x == 0) g_deg[i] = cnt < MAXD ? cnt : MAXD;
}

// ---------------- tiled SGEMM with fused epilogue ----------------
// C[M,Nc] = A[M,K] @ B[K,Nc]; writes bf16 C plus f1 = C@a[:Nc], f2 = C@a[Nc:].
// Requires BN == Nc (full output width per block) and BN/TN == 16.
template <int BM, int BN, int BK, int TM, int TN>
__global__ void sgemm_fused(const float* __restrict__ A,
                            const float* __restrict__ B,
                            __nv_bfloat16* __restrict__ Cb,
                            const float* __restrict__ avec,
                            float* __restrict__ f1,
                            float* __restrict__ f2,
                            int M, int Nc, int K,
                            long strideA, long strideB, long strideAv) {
    constexpr int THREADS = (BM / TM) * (BN / TN);
    static_assert(BN / TN == 16, "shuffle groups assume 16");
    int z = blockIdx.z;
    A    += (long)z * strideA;
    B    += (long)z * strideB;
    avec += (long)z * strideAv;
    Cb   += (long)z * M * Nc;
    f1   += (long)z * M;
    f2   += (long)z * M;

    __shared__ float As[BK][BM];
    __shared__ float Bs[BK][BN];

    int brow = blockIdx.y * BM;
    int tid  = threadIdx.x;
    int tcol = tid % 16;
    int trow = tid / 16;

    float acc[TM][TN];
#pragma unroll
    for (int i = 0; i < TM; i++)
#pragma unroll
        for (int j = 0; j < TN; j++) acc[i][j] = 0.0f;

    for (int k0 = 0; k0 < K; k0 += BK) {
        constexpr int A_LOADS = (BM * BK) / (4 * THREADS);
#pragma unroll
        for (int l = 0; l < A_LOADS; l++) {
            int idx = tid + l * THREADS;
            int r  = idx / (BK / 4);
            int c4 = idx % (BK / 4);
            float4 v = *(const float4*)&A[(long)(brow + r) * K + k0 + c4 * 4];
            As[c4 * 4 + 0][r] = v.x;
            As[c4 * 4 + 1][r] = v.y;
            As[c4 * 4 + 2][r] = v.z;
            As[c4 * 4 + 3][r] = v.w;
        }
        constexpr int B_LOADS = (BK * BN) / (4 * THREADS);
#pragma unroll
        for (int l = 0; l < B_LOADS; l++) {
            int idx = tid + l * THREADS;
            int r  = idx / (BN / 4);
            int c4 = idx % (BN / 4);
            float4 v = *(const float4*)&B[(long)(k0 + r) * Nc + c4 * 4];
            *(float4*)&Bs[r][c4 * 4] = v;
        }
        __syncthreads();
#pragma unroll
        for (int kk = 0; kk < BK; kk++) {
            float a[TM], b[TN];
#pragma unroll
            for (int i = 0; i < TM; i++) a[i] = As[kk][trow * TM + i];
#pragma unroll
            for (int j = 0; j < TN; j++) b[j] = Bs[kk][tcol * TN + j];
#pragma unroll
            for (int i = 0; i < TM; i++)
#pragma unroll
                for (int j = 0; j < TN; j++) acc[i][j] += a[i] * b[j];
        }
        __syncthreads();
    }

    // ---- fused epilogue: bf16 store + f1/f2 row dots ----
    int colBase = tcol * TN;
#pragma unroll
    for (int i = 0; i < TM; i++) {
        int r = brow + trow * TM + i;
        float p1 = 0.0f, p2 = 0.0f;
#pragma unroll
        for (int j = 0; j < TN; j++) {
            float v = acc[i][j];
            int c = colBase + j;
            p1 += v * __ldg(&avec[c]);
            p2 += v * __ldg(&avec[Nc + c]);
        }
#pragma unroll
        for (int o = 8; o; o >>= 1) {
            p1 += __shfl_down_sync(0xffffffffu, p1, o, 16);
            p2 += __shfl_down_sync(0xffffffffu, p2, o, 16);
        }
        if (tcol == 0) { f1[r] = p1; f2[r] = p2; }
#pragma unroll
        for (int j = 0; j < TN; j += 2) {
            __nv_bfloat162 bv = __float22bfloat162_rn(make_float2(acc[i][j], acc[i][j + 1]));
            *(__nv_bfloat162*)&Cb[(long)r * Nc + colBase + j] = bv;
        }
    }
}

// ---------------- block reductions ----------------
template <int BLOCK>
__device__ __forceinline__ float block_reduce(float v, float* red, bool isMax) {
    const unsigned FULL = 0xffffffffu;
#pragma unroll
    for (int o = 16; o; o >>= 1) {
        float t = __shfl_down_sync(FULL, v, o);
        v = isMax ? fmaxf(v, t) : (v + t);
    }
    int lane = threadIdx.x & 31;
    int wid  = threadIdx.x >> 5;
    constexpr int NW = BLOCK / 32;
    if (lane == 0) red[wid] = v;
    __syncthreads();
    if (wid == 0) {
        float r = (lane < NW) ? red[lane] : (isMax ? -3.4e38f : 0.0f);
#pragma unroll
        for (int o = 16; o; o >>= 1) {
            float t = __shfl_down_sync(FULL, r, o);
            r = isMax ? fmaxf(r, t) : (r + t);
        }
        if (lane == 0) red[0] = r;
    }
    __syncthreads();
    float result = red[0];
    __syncthreads();
    return result;
}

// ---------------- fused sparse attention + ELU (bf16 gather, fp32 accum) ----------------
// grid = (NN, nHeads), block = 128. Output at out[i*iStride + h*hStride + t].
template <int D>
__global__ void attn_kernel(const __nv_bfloat16* __restrict__ Whb,
                            const float* __restrict__ f1,
                            const float* __restrict__ f2,
                            float* __restrict__ out,
                            long iStride, long hStride) {
    constexpr int BLOCK = 128;
    constexpr int TPR = D / 4;          // threads per row (4 feats/thread)
    constexpr int NG  = BLOCK / TPR;    // neighbor parity groups
    int i = blockIdx.x;
    int h = blockIdx.y;
    const __nv_bfloat16* WhH = Whb + (long)h * NN * D;
    const float* f2H = f2 + (long)h * NN;
    float f1i = f1[(long)h * NN + i];

    __shared__ float w[MAXD];
    __shared__ int   nb[MAXD];
    __shared__ float red[BLOCK / 32];
    __shared__ __align__(16) float part[NG * D];

    int d   = g_deg[i];
    int tid = threadIdx.x;

    // e_j = leakyrelu(f1_i + f2_j)
    for (int k = tid; k < d; k += BLOCK) {
        int j = g_nbr[i * MAXD + k];
        nb[k] = j;
        float e = f1i + f2H[j];
        w[k] = (e > 0.0f) ? e : 0.2f * e;
    }
    __syncthreads();

    float m = -3.4e38f;
    for (int k = tid; k < d; k += BLOCK) m = fmaxf(m, w[k]);
    m = block_reduce<BLOCK>(m, red, true);

    float s = 0.0f;
    for (int k = tid; k < d; k += BLOCK) {
        float v = __expf(w[k] - m);
        w[k] = v;
        s += v;
    }
    s = block_reduce<BLOCK>(s, red, false);   // barrier: w[] visible after

    // gather: group g handles neighbors k = g, g+NG, ...; thread covers 4 feats
    int f = tid % TPR;
    int g = tid / TPR;
    float4 acc = make_float4(0.f, 0.f, 0.f, 0.f);
    if (d > 0) {
#pragma unroll 4
        for (int k = g; k < d; k += NG) {
            float wk = w[k];
            float2 raw = ((const float2*)(WhH + (long)nb[k] * D))[f];
            __nv_bfloat162 b0 = *(__nv_bfloat162*)&raw.x;
            __nv_bfloat162 b1 = *(__nv_bfloat162*)&raw.y;
            float2 c0 = __bfloat1622float2(b0);
            float2 c1 = __bfloat1622float2(b1);
            acc.x += wk * c0.x; acc.y += wk * c0.y;
            acc.z += wk * c1.x; acc.w += wk * c1.y;
        }
    } else {
        // uniform attention over all nodes (softmax of constant row)
        for (int k = g; k < NN; k += NG) {
            float2 raw = ((const float2*)(WhH + (long)k * D))[f];
            __nv_bfloat162 b0 = *(__nv_bfloat162*)&raw.x;
            __nv_bfloat162 b1 = *(__nv_bfloat162*)&raw.y;
            float2 c0 = __bfloat1622float2(b0);
            float2 c1 = __bfloat1622float2(b1);
            acc.x += c0.x; acc.y += c0.y; acc.z += c1.x; acc.w += c1.y;
        }
    }
    *(float4*)&part[g * D + f * 4] = acc;
    __syncthreads();

    if (tid < D) {
        float v = 0.0f;
#pragma unroll
        for (int gg = 0; gg < NG; gg++) v += part[gg * D + tid];
        float inv = (d > 0) ? (1.0f / s) : (1.0f / NN);
        v *= inv;
        float r = (v > 0.0f) ? v : expm1f(v);
        out[(long)i * iStride + (long)h * hStride + tid] = r;
    }
}

// ---------------- launch ----------------
extern "C" void kernel_launch(void* const* d_in, const int* in_sizes, int n_in,
                              void* d_out, int out_size) {
    const float* x     = (const float*)d_in[0];
    const float* adj   = (const float*)d_in[1];
    const int*   obs   = (const int*)  d_in[2];
    // d_in[3] = s_mat (unused)
    const float* theta = (const float*)d_in[4];
    const float* W0    = (const float*)d_in[5];
    const float* a0    = (const float*)d_in[6];
    const float* W1    = (const float*)d_in[7];
    const float* a1    = (const float*)d_in[8];
    const float* Wo    = (const float*)d_in[9];
    const float* ao    = (const float*)d_in[10];
    float* out = (float*)d_out;

    void *pH, *pWhb, *pHa, *pHc, *pWhob, *pF1, *pF2, *pF1o, *pF2o;
    cudaGetSymbolAddress(&pH,    g_h);
    cudaGetSymbolAddress(&pWhb,  g_Whb);
    cudaGetSymbolAddress(&pHa,   g_ha);
    cudaGetSymbolAddress(&pHc,   g_hc);
    cudaGetSymbolAddress(&pWhob, g_Whob);
    cudaGetSymbolAddress(&pF1,   g_f1);
    cudaGetSymbolAddress(&pF2,   g_f2);
    cudaGetSymbolAddress(&pF1o,  g_f1o);
    cudaGetSymbolAddress(&pF2o,  g_f2o);

    // 1. merge state
    prep_kernel<<<(NN * FF + 255) / 256, 256>>>(x, obs, theta);
    // 2. adjacency -> CSR
    build_csr_kernel<<<NN, 256>>>(adj);

    // ---- layer 0: Wh0 = h @ W0 (+f1/f2), then sparse attention ----
    sgemm_fused<128, 128, 16, 8, 8><<<dim3(1, NN / 128, HH), 256>>>(
        (const float*)pH, W0, (__nv_bfloat16*)pWhb, a0,
        (float*)pF1, (float*)pF2, NN, DD, FF,
        0L, (long)FF * DD, 2L * DD);
    attn_kernel<DD><<<dim3(NN, HH), 128>>>((const __nv_bfloat16*)pWhb,
                                           (const float*)pF1, (const float*)pF2,
                                           (float*)pHa, (long)DD, (long)NN * DD);

    // ---- layer 1 (output written directly in concat layout) ----
    sgemm_fused<128, 128, 16, 8, 8><<<dim3(1, NN / 128, HH), 256>>>(
        (const float*)pHa, W1, (__nv_bfloat16*)pWhb, a1,
        (float*)pF1, (float*)pF2, NN, DD, DD,
        (long)NN * DD, (long)DD * DD, 2L * DD);
    attn_kernel<DD><<<dim3(NN, HH), 128>>>((const __nv_bfloat16*)pWhb,
                                           (const float*)pF1, (const float*)pF2,
                                           (float*)pHc, (long)HH * DD, (long)DD);

    // ---- output layer ----
    sgemm_fused<128, 64, 16, 8, 4><<<dim3(1, NN / 128, 1), 256>>>(
        (const float*)pHc, Wo, (__nv_bfloat16*)pWhob, ao,
        (float*)pF1o, (float*)pF2o, NN, OUTD, HH * DD,
        0L, 0L, 0L);
    attn_kernel<OUTD><<<dim3(NN, 1), 128>>>((const __nv_bfloat16*)pWhob,
                                            (const float*)pF1o, (const float*)pF2o,
                                            out, (long)OUTD, 0L);
    (void)in_sizes; (void)n_in; (void)out_size;
}

// round 3
// speedup vs baseline: 1.8834x; 1.3116x over previous
#include <cuda_runtime.h>
#include <cuda_bf16.h>

// Problem constants
#define NN   3072
#define FF   256
#define HH   8
#define DD   128
#define OUTD 64
#define MAXD 384

// ---------------- device scratch ----------------
__device__ __align__(16) float         g_h   [NN * FF];
__device__ __align__(16) __nv_bfloat16 g_Whb [HH * NN * DD];
__device__ __align__(16) float         g_ha  [HH * NN * DD];
__device__ __align__(16) float         g_hc  [NN * HH * DD];
__device__ __align__(16) __nv_bfloat16 g_Whob[NN * OUTD];
__device__ float g_f1 [HH * NN];
__device__ float g_f2 [HH * NN];
__device__ float g_f1o[NN];
__device__ float g_f2o[NN];
__device__ int   g_nbr[NN * MAXD];
__device__ int   g_deg[NN];

// ---------------- prep: h = x + (obs==1) * theta ----------------
__global__ void prep_kernel(const float* __restrict__ x,
                            const int* __restrict__ obs,
                            const float* __restrict__ theta) {
    int idx = blockIdx.x * blockDim.x + threadIdx.x;
    if (idx >= NN * FF) return;
    int i = idx / FF;
    int t = idx - i * FF;
    float add = (obs[i] == 1) ? theta[t] : 0.0f;
    g_h[idx] = x[idx] + add;
}

// ---------------- CSR build ----------------
__global__ void build_csr_kernel(const float* __restrict__ adj) {
    int i = blockIdx.x;
    __shared__ int cnt;
    if (threadIdx.x == 0) cnt = 0;
    __syncthreads();
    const float* row = adj + (long)i * NN;
    for (int j = threadIdx.x; j < NN; j += blockDim.x) {
        if (row[j] > 0.0f) {
            int p = atomicAdd(&cnt, 1);
            if (p < MAXD) g_nbr[i * MAXD + p] = j;
        }
    }
    __syncthreads();
    if (threadIdx.x == 0) g_deg[i] = cnt < MAXD ? cnt : MAXD;
}

// ---------------- tf32 mma helpers ----------------
__device__ __forceinline__ unsigned f2tf(float f) {
    unsigned u;
    asm("cvt.rna.tf32.f32 %0, %1;" : "=r"(u) : "f"(f));
    return u;
}
__device__ __forceinline__ void mma_tf32(float c[4], const unsigned a[4], const unsigned b[2]) {
    asm("mma.sync.aligned.m16n8k8.row.col.f32.tf32.tf32.f32 "
        "{%0,%1,%2,%3}, {%4,%5,%6,%7}, {%8,%9}, {%0,%1,%2,%3};"
        : "+f"(c[0]), "+f"(c[1]), "+f"(c[2]), "+f"(c[3])
        : "r"(a[0]), "r"(a[1]), "r"(a[2]), "r"(a[3]), "r"(b[0]), "r"(b[1]));
}

// ---------------- tf32 tensor-core GEMM with fused epilogue ----------------
// C[M,Nc] = A[M,K]@B[K,Nc] (fp32 in, tf32 mma, fp32 accum).
// Writes bf16 C, plus f1 = C@avec[:Nc], f2 = C@avec[Nc:]. Requires BN == Nc.
template <int BM, int BN, int BK, int WM, int WN>
__global__ void mma_gemm(const float* __restrict__ A,
                         const float* __restrict__ B,
                         __nv_bfloat16* __restrict__ Cb,
                         const float* __restrict__ avec,
                         float* __restrict__ f1,
                         float* __restrict__ f2,
                         int M, int Nc, int K,
                         long strideA, long strideB, long strideAv) {
    constexpr int WARPS_N = BN / WN;
    constexpr int WARPS_M = BM / WM;
    constexpr int THREADS = WARPS_M * WARPS_N * 32;
    constexpr int MT = WM / 16, NT = WN / 8;
    constexpr int AP = BK + 4;
    constexpr int BP = BN + 8;

    __shared__ unsigned As[BM][AP];
    __shared__ unsigned Bs[BK][BP];
    __shared__ float f1s[BM], f2s[BM];

    int z = blockIdx.z;
    A    += (long)z * strideA;
    B    += (long)z * strideB;
    avec += (long)z * strideAv;
    Cb   += (long)z * M * Nc;
    f1   += (long)z * M;
    f2   += (long)z * M;

    int tid  = threadIdx.x;
    int brow = blockIdx.y * BM;
    int warp = tid >> 5, lane = tid & 31;
    int gid  = lane >> 2, tig = lane & 3;
    int wm   = (warp / WARPS_N) * WM;
    int wn   = (warp % WARPS_N) * WN;

    if (tid < BM) { f1s[tid] = 0.0f; f2s[tid] = 0.0f; }

    float c[MT][NT][4];
#pragma unroll
    for (int i = 0; i < MT; i++)
#pragma unroll
        for (int j = 0; j < NT; j++)
#pragma unroll
            for (int q = 0; q < 4; q++) c[i][j][q] = 0.0f;

    for (int k0 = 0; k0 < K; k0 += BK) {
        __syncthreads();
        constexpr int A_LD = BM * BK / (4 * THREADS);
#pragma unroll
        for (int l = 0; l < A_LD; l++) {
            int idx = tid + l * THREADS;
            int r  = idx / (BK / 4);
            int c4 = idx % (BK / 4);
            float4 v = *(const float4*)&A[(long)(brow + r) * K + k0 + c4 * 4];
            As[r][c4 * 4 + 0] = f2tf(v.x);
            As[r][c4 * 4 + 1] = f2tf(v.y);
            As[r][c4 * 4 + 2] = f2tf(v.z);
            As[r][c4 * 4 + 3] = f2tf(v.w);
        }
        constexpr int B_LD = BK * BN / (4 * THREADS);
#pragma unroll
        for (int l = 0; l < B_LD; l++) {
            int idx = tid + l * THREADS;
            int r  = idx / (BN / 4);
            int c4 = idx % (BN / 4);
            float4 v = *(const float4*)&B[(long)(k0 + r) * Nc + c4 * 4];
            Bs[r][c4 * 4 + 0] = f2tf(v.x);
            Bs[r][c4 * 4 + 1] = f2tf(v.y);
            Bs[r][c4 * 4 + 2] = f2tf(v.z);
            Bs[r][c4 * 4 + 3] = f2tf(v.w);
        }
        __syncthreads();
#pragma unroll
        for (int kk = 0; kk < BK; kk += 8) {
            unsigned a[MT][4], b[NT][2];
#pragma unroll
            for (int mt = 0; mt < MT; mt++) {
                int r0 = wm + mt * 16 + gid;
                a[mt][0] = As[r0][kk + tig];
                a[mt][1] = As[r0 + 8][kk + tig];
                a[mt][2] = As[r0][kk + tig + 4];
                a[mt][3] = As[r0 + 8][kk + tig + 4];
            }
#pragma unroll
            for (int nt = 0; nt < NT; nt++) {
                int cn = wn + nt * 8 + gid;
                b[nt][0] = Bs[kk + tig][cn];
                b[nt][1] = Bs[kk + tig + 4][cn];
            }
#pragma unroll
            for (int mt = 0; mt < MT; mt++)
#pragma unroll
                for (int nt = 0; nt < NT; nt++)
                    mma_tf32(c[mt][nt], a[mt], b[nt]);
        }
    }

    // ---- epilogue: bf16 store + f1/f2 ----
#pragma unroll
    for (int mt = 0; mt < MT; mt++) {
        int rl0 = wm + mt * 16 + gid;
        int rl1 = rl0 + 8;
        float p10 = 0.f, p20 = 0.f, p11 = 0.f, p21 = 0.f;
#pragma unroll
        for (int nt = 0; nt < NT; nt++) {
            int col = wn + nt * 8 + tig * 2;
            float a0 = __ldg(&avec[col]),      a1 = __ldg(&avec[col + 1]);
            float b0 = __ldg(&avec[Nc + col]), b1 = __ldg(&avec[Nc + col + 1]);
            float c0 = c[mt][nt][0], c1 = c[mt][nt][1];
            float c2 = c[mt][nt][2], c3 = c[mt][nt][3];
            p10 += c0 * a0 + c1 * a1;
            p20 += c0 * b0 + c1 * b1;
            p11 += c2 * a0 + c3 * a1;
            p21 += c2 * b0 + c3 * b1;
            *(__nv_bfloat162*)&Cb[(long)(brow + rl0) * Nc + col] =
                __float22bfloat162_rn(make_float2(c0, c1));
            *(__nv_bfloat162*)&Cb[(long)(brow + rl1) * Nc + col] =
                __float22bfloat162_rn(make_float2(c2, c3));
        }
#pragma unroll
        for (int o = 2; o; o >>= 1) {
            p10 += __shfl_down_sync(0xffffffffu, p10, o, 4);
            p20 += __shfl_down_sync(0xffffffffu, p20, o, 4);
            p11 += __shfl_down_sync(0xffffffffu, p11, o, 4);
            p21 += __shfl_down_sync(0xffffffffu, p21, o, 4);
        }
        if (tig == 0) {
            atomicAdd(&f1s[rl0], p10);
            atomicAdd(&f2s[rl0], p20);
            atomicAdd(&f1s[rl1], p11);
            atomicAdd(&f2s[rl1], p21);
        }
    }
    __syncthreads();
    if (tid < BM) {
        f1[brow + tid] = f1s[tid];
        f2[brow + tid] = f2s[tid];
    }
}

// ---------------- block reductions ----------------
template <int BLOCK>
__device__ __forceinline__ float block_reduce(float v, float* red, bool isMax) {
    const unsigned FULL = 0xffffffffu;
#pragma unroll
    for (int o = 16; o; o >>= 1) {
        float t = __shfl_down_sync(FULL, v, o);
        v = isMax ? fmaxf(v, t) : (v + t);
    }
    int lane = threadIdx.x & 31;
    int wid  = threadIdx.x >> 5;
    constexpr int NW = BLOCK / 32;
    if (lane == 0) red[wid] = v;
    __syncthreads();
    if (wid == 0) {
        float r = (lane < NW) ? red[lane] : (isMax ? -3.4e38f : 0.0f);
#pragma unroll
        for (int o = 16; o; o >>= 1) {
            float t = __shfl_down_sync(FULL, r, o);
            r = isMax ? fmaxf(r, t) : (r + t);
        }
        if (lane == 0) red[0] = r;
    }
    __syncthreads();
    float result = red[0];
    __syncthreads();
    return result;
}

// ---------------- fused sparse attention + ELU ----------------
// grid = (NN, nHeads), block = 128. 8 features/thread, fused {w,off} smem.
template <int D>
__global__ void attn_kernel(const __nv_bfloat16* __restrict__ Whb,
                            const float* __restrict__ f1,
                            const float* __restrict__ f2,
                            float* __restrict__ out,
                            int iStride, int hStride) {
    constexpr int BLOCK = 128;
    constexpr int TPR = D / 8;          // threads per row, 8 feats/thread
    constexpr int NG  = BLOCK / TPR;    // neighbor parity groups
    int i = blockIdx.x;
    int h = blockIdx.y;
    const __nv_bfloat16* WhH = Whb + h * (NN * D);
    const float* f2H = f2 + h * NN;
    float f1i = f1[h * NN + i];

    __shared__ __align__(16) float2 wn[MAXD];   // .x = weight, .y = bitcast(j*D)
    __shared__ float red[BLOCK / 32];
    __shared__ __align__(16) float part[NG * D];

    int d   = g_deg[i];
    int tid = threadIdx.x;

    for (int k = tid; k < d; k += BLOCK) {
        int j = g_nbr[i * MAXD + k];
        float e = f1i + f2H[j];
        e = (e > 0.0f) ? e : 0.2f * e;
        wn[k] = make_float2(e, __int_as_float(j * D));
    }
    __syncthreads();

    float m = -3.4e38f;
    for (int k = tid; k < d; k += BLOCK) m = fmaxf(m, wn[k].x);
    m = block_reduce<BLOCK>(m, red, true);

    float s = 0.0f;
    for (int k = tid; k < d; k += BLOCK) {
        float v = __expf(wn[k].x - m);
        wn[k].x = v;
        s += v;
    }
    s = block_reduce<BLOCK>(s, red, false);   // barrier: wn visible after

    int f = tid % TPR;
    int g = tid / TPR;
    const __nv_bfloat16* base = WhH + f * 8;
    float a0 = 0.f, a1 = 0.f, a2 = 0.f, a3 = 0.f, a4 = 0.f, a5 = 0.f, a6 = 0.f, a7 = 0.f;
    if (d > 0) {
#pragma unroll 2
        for (int k = g; k < d; k += NG) {
            float2 p = wn[k];
            float wk = p.x;
            uint4 raw = *(const uint4*)(base + __float_as_int(p.y));
            float2 c0 = __bfloat1622float2(*(__nv_bfloat162*)&raw.x);
            float2 c1 = __bfloat1622float2(*(__nv_bfloat162*)&raw.y);
            float2 c2 = __bfloat1622float2(*(__nv_bfloat162*)&raw.z);
            float2 c3 = __bfloat1622float2(*(__nv_bfloat162*)&raw.w);
            a0 += wk * c0.x; a1 += wk * c0.y;
            a2 += wk * c1.x; a3 += wk * c1.y;
            a4 += wk * c2.x; a5 += wk * c2.y;
            a6 += wk * c3.x; a7 += wk * c3.y;
        }
    } else {
        for (int k = g; k < NN; k += NG) {
            uint4 raw = *(const uint4*)(base + k * D);
            float2 c0 = __bfloat1622float2(*(__nv_bfloat162*)&raw.x);
            float2 c1 = __bfloat1622float2(*(__nv_bfloat162*)&raw.y);
            float2 c2 = __bfloat1622float2(*(__nv_bfloat162*)&raw.z);
            float2 c3 = __bfloat1622float2(*(__nv_bfloat162*)&raw.w);
            a0 += c0.x; a1 += c0.y; a2 += c1.x; a3 += c1.y;
            a4 += c2.x; a5 += c2.y; a6 += c3.x; a7 += c3.y;
        }
    }
    *(float4*)&part[g * D + f * 8]     = make_float4(a0, a1, a2, a3);
    *(float4*)&part[g * D + f * 8 + 4] = make_float4(a4, a5, a6, a7);
    __syncthreads();

    if (tid < D) {
        float v = 0.0f;
#pragma unroll
        for (int gg = 0; gg < NG; gg++) v += part[gg * D + tid];
        float inv = (d > 0) ? (1.0f / s) : (1.0f / NN);
        v *= inv;
        float r = (v > 0.0f) ? v : expm1f(v);
        out[i * iStride + h * hStride + tid] = r;
    }
}

// ---------------- launch ----------------
extern "C" void kernel_launch(void* const* d_in, const int* in_sizes, int n_in,
                              void* d_out, int out_size) {
    const float* x     = (const float*)d_in[0];
    const float* adj   = (const float*)d_in[1];
    const int*   obs   = (const int*)  d_in[2];
    // d_in[3] = s_mat (unused)
    const float* theta = (const float*)d_in[4];
    const float* W0    = (const float*)d_in[5];
    const float* a0    = (const float*)d_in[6];
    const float* W1    = (const float*)d_in[7];
    const float* a1    = (const float*)d_in[8];
    const float* Wo    = (const float*)d_in[9];
    const float* ao    = (const float*)d_in[10];
    float* out = (float*)d_out;

    void *pH, *pWhb, *pHa, *pHc, *pWhob, *pF1, *pF2, *pF1o, *pF2o;
    cudaGetSymbolAddress(&pH,    g_h);
    cudaGetSymbolAddress(&pWhb,  g_Whb);
    cudaGetSymbolAddress(&pHa,   g_ha);
    cudaGetSymbolAddress(&pHc,   g_hc);
    cudaGetSymbolAddress(&pWhob, g_Whob);
    cudaGetSymbolAddress(&pF1,   g_f1);
    cudaGetSymbolAddress(&pF2,   g_f2);
    cudaGetSymbolAddress(&pF1o,  g_f1o);
    cudaGetSymbolAddress(&pF2o,  g_f2o);

    prep_kernel<<<(NN * FF + 255) / 256, 256>>>(x, obs, theta);
    build_csr_kernel<<<NN, 256>>>(adj);

    // ---- layer 0 ----
    mma_gemm<128, 128, 16, 64, 32><<<dim3(1, NN / 128, HH), 256>>>(
        (const float*)pH, W0, (__nv_bfloat16*)pWhb, a0,
        (float*)pF1, (float*)pF2, NN, DD, FF,
        0L, (long)FF * DD, 2L * DD);
    attn_kernel<DD><<<dim3(NN, HH), 128>>>((const __nv_bfloat16*)pWhb,
                                           (const float*)pF1, (const float*)pF2,
                                           (float*)pHa, DD, NN * DD);

    // ---- layer 1 (output written directly in concat layout) ----
    mma_gemm<128, 128, 16, 64, 32><<<dim3(1, NN / 128, HH), 256>>>(
        (const float*)pHa, W1, (__nv_bfloat16*)pWhb, a1,
        (float*)pF1, (float*)pF2, NN, DD, DD,
        (long)NN * DD, (long)DD * DD, 2L * DD);
    attn_kernel<DD><<<dim3(NN, HH), 128>>>((const __nv_bfloat16*)pWhb,
                                           (const float*)pF1, (const float*)pF2,
                                           (float*)pHc, HH * DD, DD);

    // ---- output layer ----
    mma_gemm<128, 64, 16, 32, 32><<<dim3(1, NN / 128, 1), 256>>>(
        (const float*)pHc, Wo, (__nv_bfloat16*)pWhob, ao,
        (float*)pF1o, (float*)pF2o, NN, OUTD, HH * DD,
        0L, 0L, 0L);
    attn_kernel<OUTD><<<dim3(NN, 1), 128>>>((const __nv_bfloat16*)pWhob,
                                            (const float*)pF1o, (const float*)pF2o,
                                            out, OUTD, 0);
    (void)in_sizes; (void)n_in; (void)out_size;
}

// round 4
// speedup vs baseline: 2.2091x; 1.1729x over previous
#include <cuda_runtime.h>
#include <cuda_bf16.h>

// Problem constants
#define NN   3072
#define FF   256
#define HH   8
#define DD   128
#define OUTD 64
#define MAXD 384

// ---------------- device scratch ----------------
__device__ __align__(16) __nv_bfloat16 g_Whb [HH * NN * DD];
__device__ __align__(16) float         g_ha  [HH * NN * DD];
__device__ __align__(16) float         g_hc  [NN * HH * DD];
__device__ __align__(16) __nv_bfloat16 g_Whob[NN * OUTD];
__device__ float g_f1 [HH * NN];
__device__ float g_f2 [HH * NN];
__device__ float g_f1o[NN];
__device__ float g_f2o[NN];
__device__ int   g_nbr[NN * MAXD];
__device__ int   g_deg[NN];

// ---------------- CSR build (float4) ----------------
__global__ void build_csr_kernel(const float* __restrict__ adj) {
    int i = blockIdx.x;
    __shared__ int cnt;
    if (threadIdx.x == 0) cnt = 0;
    __syncthreads();
    const float4* row = (const float4*)(adj + (long)i * NN);
    for (int q = threadIdx.x; q < NN / 4; q += blockDim.x) {
        float4 v = row[q];
        int j = 4 * q;
        if (v.x > 0.0f) { int p = atomicAdd(&cnt, 1); if (p < MAXD) g_nbr[i * MAXD + p] = j; }
        if (v.y > 0.0f) { int p = atomicAdd(&cnt, 1); if (p < MAXD) g_nbr[i * MAXD + p] = j + 1; }
        if (v.z > 0.0f) { int p = atomicAdd(&cnt, 1); if (p < MAXD) g_nbr[i * MAXD + p] = j + 2; }
        if (v.w > 0.0f) { int p = atomicAdd(&cnt, 1); if (p < MAXD) g_nbr[i * MAXD + p] = j + 3; }
    }
    __syncthreads();
    if (threadIdx.x == 0) g_deg[i] = cnt < MAXD ? cnt : MAXD;
}

// ---------------- tf32 mma helpers ----------------
__device__ __forceinline__ unsigned f2tf(float f) {
    unsigned u;
    asm("cvt.rna.tf32.f32 %0, %1;" : "=r"(u) : "f"(f));
    return u;
}
__device__ __forceinline__ void mma_tf32(float c[4], const unsigned a[4], const unsigned b[2]) {
    asm("mma.sync.aligned.m16n8k8.row.col.f32.tf32.tf32.f32 "
        "{%0,%1,%2,%3}, {%4,%5,%6,%7}, {%8,%9}, {%0,%1,%2,%3};"
        : "+f"(c[0]), "+f"(c[1]), "+f"(c[2]), "+f"(c[3])
        : "r"(a[0]), "r"(a[1]), "r"(a[2]), "r"(a[3]), "r"(b[0]), "r"(b[1]));
}

// ---------------- tf32 tensor-core GEMM with fused epilogue ----------------
// C[M,Nc] = A[M,K]@B[K,Nc]. Optional fused A-prep: A += (obs==1)*theta (layer 0).
// Writes bf16 C + f1 = C@avec[:Nc], f2 = C@avec[Nc:]. Requires BN == Nc.
template <int BM, int BN, int BK, int WM, int WN, bool FUSE_THETA>
__global__ void mma_gemm(const float* __restrict__ A,
                         const float* __restrict__ B,
                         __nv_bfloat16* __restrict__ Cb,
                         const float* __restrict__ avec,
                         float* __restrict__ f1,
                         float* __restrict__ f2,
                         int M, int Nc, int K,
                         long strideA, long strideB, long strideAv,
                         const int* __restrict__ obs,
                         const float* __restrict__ theta) {
    constexpr int WARPS_N = BN / WN;
    constexpr int WARPS_M = BM / WM;
    constexpr int THREADS = WARPS_M * WARPS_N * 32;
    constexpr int MT = WM / 16, NT = WN / 8;
    constexpr int AP = BK + 4;
    constexpr int BP = BN + 8;

    __shared__ unsigned As[BM][AP];
    __shared__ unsigned Bs[BK][BP];
    __shared__ float f1s[BM], f2s[BM];

    int z = blockIdx.z;
    A    += (long)z * strideA;
    B    += (long)z * strideB;
    avec += (long)z * strideAv;
    Cb   += (long)z * M * Nc;
    f1   += (long)z * M;
    f2   += (long)z * M;

    int tid  = threadIdx.x;
    int brow = blockIdx.y * BM;
    int warp = tid >> 5, lane = tid & 31;
    int gid  = lane >> 2, tig = lane & 3;
    int wm   = (warp / WARPS_N) * WM;
    int wn   = (warp % WARPS_N) * WN;

    if (tid < BM) { f1s[tid] = 0.0f; f2s[tid] = 0.0f; }

    float c[MT][NT][4];
#pragma unroll
    for (int i = 0; i < MT; i++)
#pragma unroll
        for (int j = 0; j < NT; j++)
#pragma unroll
            for (int q = 0; q < 4; q++) c[i][j][q] = 0.0f;

    for (int k0 = 0; k0 < K; k0 += BK) {
        __syncthreads();
        constexpr int A_LD = BM * BK / (4 * THREADS);
#pragma unroll
        for (int l = 0; l < A_LD; l++) {
            int idx = tid + l * THREADS;
            int r  = idx / (BK / 4);
            int c4 = idx % (BK / 4);
            float4 v = *(const float4*)&A[(long)(brow + r) * K + k0 + c4 * 4];
            if (FUSE_THETA) {
                if (obs[brow + r] == 1) {
                    const float4 t = *(const float4*)&theta[k0 + c4 * 4];
                    v.x += t.x; v.y += t.y; v.z += t.z; v.w += t.w;
                }
            }
            As[r][c4 * 4 + 0] = f2tf(v.x);
            As[r][c4 * 4 + 1] = f2tf(v.y);
            As[r][c4 * 4 + 2] = f2tf(v.z);
            As[r][c4 * 4 + 3] = f2tf(v.w);
        }
        constexpr int B_LD = BK * BN / (4 * THREADS);
#pragma unroll
        for (int l = 0; l < B_LD; l++) {
            int idx = tid + l * THREADS;
            int r  = idx / (BN / 4);
            int c4 = idx % (BN / 4);
            float4 v = *(const float4*)&B[(long)(k0 + r) * Nc + c4 * 4];
            Bs[r][c4 * 4 + 0] = f2tf(v.x);
            Bs[r][c4 * 4 + 1] = f2tf(v.y);
            Bs[r][c4 * 4 + 2] = f2tf(v.z);
            Bs[r][c4 * 4 + 3] = f2tf(v.w);
        }
        __syncthreads();
#pragma unroll
        for (int kk = 0; kk < BK; kk += 8) {
            unsigned a[MT][4], b[NT][2];
#pragma unroll
            for (int mt = 0; mt < MT; mt++) {
                int r0 = wm + mt * 16 + gid;
                a[mt][0] = As[r0][kk + tig];
                a[mt][1] = As[r0 + 8][kk + tig];
                a[mt][2] = As[r0][kk + tig + 4];
                a[mt][3] = As[r0 + 8][kk + tig + 4];
            }
#pragma unroll
            for (int nt = 0; nt < NT; nt++) {
                int cn = wn + nt * 8 + gid;
                b[nt][0] = Bs[kk + tig][cn];
                b[nt][1] = Bs[kk + tig + 4][cn];
            }
#pragma unroll
            for (int mt = 0; mt < MT; mt++)
#pragma unroll
                for (int nt = 0; nt < NT; nt++)
                    mma_tf32(c[mt][nt], a[mt], b[nt]);
        }
    }

    // ---- epilogue: bf16 store + f1/f2 ----
#pragma unroll
    for (int mt = 0; mt < MT; mt++) {
        int rl0 = wm + mt * 16 + gid;
        int rl1 = rl0 + 8;
        float p10 = 0.f, p20 = 0.f, p11 = 0.f, p21 = 0.f;
#pragma unroll
        for (int nt = 0; nt < NT; nt++) {
            int col = wn + nt * 8 + tig * 2;
            float a0 = __ldg(&avec[col]),      a1 = __ldg(&avec[col + 1]);
            float b0 = __ldg(&avec[Nc + col]), b1 = __ldg(&avec[Nc + col + 1]);
            float c0 = c[mt][nt][0], c1 = c[mt][nt][1];
            float c2 = c[mt][nt][2], c3 = c[mt][nt][3];
            p10 += c0 * a0 + c1 * a1;
            p20 += c0 * b0 + c1 * b1;
            p11 += c2 * a0 + c3 * a1;
            p21 += c2 * b0 + c3 * b1;
            *(__nv_bfloat162*)&Cb[(long)(brow + rl0) * Nc + col] =
                __float22bfloat162_rn(make_float2(c0, c1));
            *(__nv_bfloat162*)&Cb[(long)(brow + rl1) * Nc + col] =
                __float22bfloat162_rn(make_float2(c2, c3));
        }
#pragma unroll
        for (int o = 2; o; o >>= 1) {
            p10 += __shfl_down_sync(0xffffffffu, p10, o, 4);
            p20 += __shfl_down_sync(0xffffffffu, p20, o, 4);
            p11 += __shfl_down_sync(0xffffffffu, p11, o, 4);
            p21 += __shfl_down_sync(0xffffffffu, p21, o, 4);
        }
        if (tig == 0) {
            atomicAdd(&f1s[rl0], p10);
            atomicAdd(&f2s[rl0], p20);
            atomicAdd(&f1s[rl1], p11);
            atomicAdd(&f2s[rl1], p21);
        }
    }
    __syncthreads();
    if (tid < BM) {
        f1[brow + tid] = f1s[tid];
        f2[brow + tid] = f2s[tid];
    }
}

// ---------------- bf16x2 -> 2 floats (exact) ----------------
__device__ __forceinline__ float2 bf2f(unsigned u) {
    float2 r;
    r.x = __int_as_float(u << 16);
    r.y = __int_as_float(u & 0xffff0000u);
    return r;
}

// ---------------- warp-per-(i,h) sparse attention + ELU, barrier-free ----------------
// block = 128 (4 warps, 4 consecutive i), grid = (NN/4, nHeads).
template <int D>
__global__ void attn_warp(const __nv_bfloat16* __restrict__ Whb,
                          const float* __restrict__ f1,
                          const float* __restrict__ f2,
                          float* __restrict__ out,
                          int iStride, int hStride) {
    constexpr int WPB = 4;
    constexpr int FPL = D / 32;            // floats per lane: 4 (D=128) or 2 (D=64)
    __shared__ __align__(16) float2 wns[WPB][MAXD];   // {exp_w, bitcast(byte_off)}
    int warp = threadIdx.x >> 5, lane = threadIdx.x & 31;
    int i = blockIdx.x * WPB + warp;
    int h = blockIdx.y;
    const __nv_bfloat16* WhH = Whb + h * (NN * D);
    const float* f2H = f2 + h * NN;
    float f1i = f1[h * NN + i];
    int d = g_deg[i];
    float2* w = wns[warp];
    const unsigned FULL = 0xffffffffu;

    // pass A: e = leakyrelu(f1_i + f2_j), track max
    float m = -3.4e38f;
    for (int k = lane; k < d; k += 32) {
        int j = g_nbr[i * MAXD + k];
        float e = f1i + f2H[j];
        e = (e > 0.0f) ? e : 0.2f * e;
        m = fmaxf(m, e);
        w[k] = make_float2(e, __int_as_float(j * (D * 2)));
    }
#pragma unroll
    for (int o = 16; o; o >>= 1) m = fmaxf(m, __shfl_xor_sync(FULL, m, o));

    // pass B: exp + sum (each lane touches only its own k's)
    float s = 0.0f;
    for (int k = lane; k < d; k += 32) {
        float v = __expf(w[k].x - m);
        w[k].x = v;
        s += v;
    }
#pragma unroll
    for (int o = 16; o; o >>= 1) s += __shfl_xor_sync(FULL, s, o);
    __syncwarp();

    // pass C: gather — all 32 lanes per neighbor, FPL feats/lane
    const char* basep = (const char*)WhH + lane * (FPL * 2);
    float acc[FPL];
#pragma unroll
    for (int q = 0; q < FPL; q++) acc[q] = 0.0f;

    if (d > 0) {
#pragma unroll 4
        for (int k = 0; k < d; k++) {
            float2 p = w[k];
            float wk = p.x;
            int off = __float_as_int(p.y);
            if (FPL == 4) {
                uint2 raw = *(const uint2*)(basep + off);
                float2 c0 = bf2f(raw.x);
                float2 c1 = bf2f(raw.y);
                acc[0] += wk * c0.x; acc[1] += wk * c0.y;
                acc[2] += wk * c1.x; acc[3] += wk * c1.y;
            } else {
                unsigned raw = *(const unsigned*)(basep + off);
                float2 c0 = bf2f(raw);
                acc[0] += wk * c0.x; acc[1] += wk * c0.y;
            }
        }
        float inv = 1.0f / s;
#pragma unroll
        for (int q = 0; q < FPL; q++) acc[q] *= inv;
    } else {
        // uniform attention over all nodes (softmax of constant row)
        for (int k = 0; k < NN; k++) {
            if (FPL == 4) {
                uint2 raw = *(const uint2*)(basep + k * (D * 2));
                float2 c0 = bf2f(raw.x);
                float2 c1 = bf2f(raw.y);
                acc[0] += c0.x; acc[1] += c0.y; acc[2] += c1.x; acc[3] += c1.y;
            } else {
                unsigned raw = *(const unsigned*)(basep + k * (D * 2));
                float2 c0 = bf2f(raw);
                acc[0] += c0.x; acc[1] += c0.y;
            }
        }
#pragma unroll
        for (int q = 0; q < FPL; q++) acc[q] *= (1.0f / NN);
    }

    // ELU + coalesced store
    float* op = out + (long)i * iStride + h * hStride + lane * FPL;
#pragma unroll
    for (int q = 0; q < FPL; q++) acc[q] = (acc[q] > 0.0f) ? acc[q] : expm1f(acc[q]);
    if (FPL == 4) *(float4*)op = make_float4(acc[0], acc[1], acc[2], acc[3]);
    else          *(float2*)op = make_float2(acc[0], acc[1]);
}

// ---------------- launch ----------------
extern "C" void kernel_launch(void* const* d_in, const int* in_sizes, int n_in,
                              void* d_out, int out_size) {
    const float* x     = (const float*)d_in[0];
    const float* adj   = (const float*)d_in[1];
    const int*   obs   = (const int*)  d_in[2];
    // d_in[3] = s_mat (unused)
    const float* theta = (const float*)d_in[4];
    const float* W0    = (const float*)d_in[5];
    const float* a0    = (const float*)d_in[6];
    const float* W1    = (const float*)d_in[7];
    const float* a1    = (const float*)d_in[8];
    const float* Wo    = (const float*)d_in[9];
    const float* ao    = (const float*)d_in[10];
    float* out = (float*)d_out;

    void *pWhb, *pHa, *pHc, *pWhob, *pF1, *pF2, *pF1o, *pF2o;
    cudaGetSymbolAddress(&pWhb,  g_Whb);
    cudaGetSymbolAddress(&pHa,   g_ha);
    cudaGetSymbolAddress(&pHc,   g_hc);
    cudaGetSymbolAddress(&pWhob, g_Whob);
    cudaGetSymbolAddress(&pF1,   g_f1);
    cudaGetSymbolAddress(&pF2,   g_f2);
    cudaGetSymbolAddress(&pF1o,  g_f1o);
    cudaGetSymbolAddress(&pF2o,  g_f2o);

    build_csr_kernel<<<NN, 256>>>(adj);

    // ---- layer 0 (theta merge fused into A-load) ----
    mma_gemm<128, 128, 32, 64, 32, true><<<dim3(1, NN / 128, HH), 256>>>(
        x, W0, (__nv_bfloat16*)pWhb, a0,
        (float*)pF1, (float*)pF2, NN, DD, FF,
        0L, (long)FF * DD, 2L * DD, obs, theta);
    attn_warp<DD><<<dim3(NN / 4, HH), 128>>>((const __nv_bfloat16*)pWhb,
                                             (const float*)pF1, (const float*)pF2,
                                             (float*)pHa, DD, NN * DD);

    // ---- layer 1 (output written directly in concat layout) ----
    mma_gemm<128, 128, 32, 64, 32, false><<<dim3(1, NN / 128, HH), 256>>>(
        (const float*)pHa, W1, (__nv_bfloat16*)pWhb, a1,
        (float*)pF1, (float*)pF2, NN, DD, DD,
        (long)NN * DD, (long)DD * DD, 2L * DD, nullptr, nullptr);
    attn_warp<DD><<<dim3(NN / 4, HH), 128>>>((const __nv_bfloat16*)pWhb,
                                             (const float*)pF1, (const float*)pF2,
                                             (float*)pHc, HH * DD, DD);

    // ---- output layer ----
    mma_gemm<128, 64, 32, 32, 32, false><<<dim3(1, NN / 128, 1), 256>>>(
        (const float*)pHc, Wo, (__nv_bfloat16*)pWhob, ao,
        (float*)pF1o, (float*)pF2o, NN, OUTD, HH * DD,
        0L, 0L, 0L, nullptr, nullptr);
    attn_warp<OUTD><<<dim3(NN / 4, 1), 128>>>((const __nv_bfloat16*)pWhob,
                                              (const float*)pF1o, (const float*)pF2o,
                                              out, OUTD, 0);
    (void)in_sizes; (void)n_in; (void)out_size;
}

// round 7
// speedup vs baseline: 2.4616x; 1.1143x over previous
#include <cuda_runtime.h>
#include <cuda_bf16.h>

// Problem constants
#define NN   3072
#define FF   256
#define HH   8
#define DD   128
#define OUTD 64
#define MAXD 384
#define SPLITK 4

// ---------------- device scratch ----------------
__device__ __align__(16) __nv_bfloat16 g_Whb [HH * NN * DD];
__device__ __align__(16) float         g_ha  [HH * NN * DD];
__device__ __align__(16) float         g_hc  [NN * HH * DD];
__device__ __align__(16) float         g_who [SPLITK * NN * OUTD];
__device__ __align__(16) __nv_bfloat16 g_Whob[NN * OUTD];
__device__ __align__(16) float         g_tw  [HH * DD];       // theta @ W0 per head
__device__ float g_f1 [HH * NN];
__device__ float g_f2 [HH * NN];
__device__ float g_f1o[NN];
__device__ float g_f2o[NN];
__device__ int   g_nbr[NN * MAXD];
__device__ int   g_deg[NN];

// ---------------- theta @ W0 precompute (per head) ----------------
__global__ void thetaW_kernel(const float* __restrict__ theta,
                              const float* __restrict__ W0) {
    int h = blockIdx.x;
    int c = threadIdx.x;            // 0..DD-1
    float s = 0.0f;
    const float* Wh = W0 + (long)h * FF * DD + c;
#pragma unroll 4
    for (int k = 0; k < FF; k++) s += theta[k] * Wh[(long)k * DD];
    g_tw[h * DD + c] = s;
}

// ---------------- CSR build (float4) ----------------
__global__ void build_csr_kernel(const float* __restrict__ adj) {
    int i = blockIdx.x;
    __shared__ int cnt;
    if (threadIdx.x == 0) cnt = 0;
    __syncthreads();
    const float4* row = (const float4*)(adj + (long)i * NN);
    for (int q = threadIdx.x; q < NN / 4; q += blockDim.x) {
        float4 v = row[q];
        int j = 4 * q;
        if (v.x > 0.0f) { int p = atomicAdd(&cnt, 1); if (p < MAXD) g_nbr[i * MAXD + p] = j; }
        if (v.y > 0.0f) { int p = atomicAdd(&cnt, 1); if (p < MAXD) g_nbr[i * MAXD + p] = j + 1; }
        if (v.z > 0.0f) { int p = atomicAdd(&cnt, 1); if (p < MAXD) g_nbr[i * MAXD + p] = j + 2; }
        if (v.w > 0.0f) { int p = atomicAdd(&cnt, 1); if (p < MAXD) g_nbr[i * MAXD + p] = j + 3; }
    }
    __syncthreads();
    if (threadIdx.x == 0) g_deg[i] = cnt < MAXD ? cnt : MAXD;
}

// ---------------- mma / cp.async helpers ----------------
__device__ __forceinline__ unsigned f2tf(unsigned bits) {
    unsigned u;
    asm("cvt.rna.tf32.f32 %0, %1;" : "=r"(u) : "r"(bits));
    return u;
}
__device__ __forceinline__ void mma_tf32(float c[4], const unsigned a[4], const unsigned b[2]) {
    asm("mma.sync.aligned.m16n8k8.row.col.f32.tf32.tf32.f32 "
        "{%0,%1,%2,%3}, {%4,%5,%6,%7}, {%8,%9}, {%0,%1,%2,%3};"
        : "+f"(c[0]), "+f"(c[1]), "+f"(c[2]), "+f"(c[3])
        : "r"(a[0]), "r"(a[1]), "r"(a[2]), "r"(a[3]), "r"(b[0]), "r"(b[1]));
}
__device__ __forceinline__ void cpa16(void* smem_dst, const void* gsrc) {
    unsigned saddr = (unsigned)__cvta_generic_to_shared(smem_dst);
    asm volatile("cp.async.ca.shared.global [%0], [%1], 16;" :: "r"(saddr), "l"(gsrc));
}
__device__ __forceinline__ void cpa_commit() { asm volatile("cp.async.commit_group;"); }
template <int N>
__device__ __forceinline__ void cpa_wait() { asm volatile("cp.async.wait_group %0;" :: "n"(N)); }

// ---------------- pipelined tf32 GEMM + fused epilogue ----------------
// C[M,Nc]=A[M,K]@B[K,Nc]; bf16 C + f1/f2 dots. BN==Nc.
// fp32 staged raw via cp.async; cvt.rna.tf32 applied at fragment load (exact RN numerics).
// FUSE_THETA: epilogue adds seed_row * g_tw[head] before store/dots.
template <int BM, int BN, int BK, int WM, int WN, bool FUSE_THETA>
__global__ void mma_gemm(const float* __restrict__ A,
                         const float* __restrict__ B,
                         __nv_bfloat16* __restrict__ Cb,
                         const float* __restrict__ avec,
                         float* __restrict__ f1,
                         float* __restrict__ f2,
                         int M, int Nc, int K,
                         long strideA, long strideB, long strideAv,
                         const int* __restrict__ obs) {
    constexpr int WARPS_N = BN / WN;
    constexpr int WARPS_M = BM / WM;
    constexpr int THREADS = WARPS_M * WARPS_N * 32;
    constexpr int MT = WM / 16, NT = WN / 8;
    constexpr int AP = BK + 4;
    constexpr int BP = BN + 8;
    constexpr int A_OPS = BM * BK / (4 * THREADS);
    constexpr int B_OPS = BK * BN / (4 * THREADS);

    __shared__ unsigned As[2][BM][AP];
    __shared__ unsigned Bs[2][BK][BP];
    __shared__ float f1s[BM], f2s[BM];

    int z = blockIdx.z;
    A    += (long)z * strideA;
    B    += (long)z * strideB;
    avec += (long)z * strideAv;
    Cb   += (long)z * M * Nc;
    f1   += (long)z * M;
    f2   += (long)z * M;

    int tid  = threadIdx.x;
    int brow = blockIdx.y * BM;
    int warp = tid >> 5, lane = tid & 31;
    int gid  = lane >> 2, tig = lane & 3;
    int wm   = (warp / WARPS_N) * WM;
    int wn   = (warp % WARPS_N) * WN;

    if (tid < BM) { f1s[tid] = 0.0f; f2s[tid] = 0.0f; }

    float c[MT][NT][4];
#pragma unroll
    for (int i = 0; i < MT; i++)
#pragma unroll
        for (int j = 0; j < NT; j++)
#pragma unroll
            for (int q = 0; q < 4; q++) c[i][j][q] = 0.0f;

    const int KT = K / BK;
    auto issue = [&](int kt, int s) {
        int k0 = kt * BK;
#pragma unroll
        for (int l = 0; l < A_OPS; l++) {
            int idx = tid + l * THREADS;
            int r  = idx / (BK / 4);
            int c4 = idx % (BK / 4);
            cpa16(&As[s][r][c4 * 4], &A[(long)(brow + r) * K + k0 + c4 * 4]);
        }
#pragma unroll
        for (int l = 0; l < B_OPS; l++) {
            int idx = tid + l * THREADS;
            int r  = idx / (BN / 4);
            int c4 = idx % (BN / 4);
            cpa16(&Bs[s][r][c4 * 4], &B[(long)(k0 + r) * Nc + c4 * 4]);
        }
        cpa_commit();
    };
    auto compute = [&](int s) {
#pragma unroll
        for (int kk = 0; kk < BK; kk += 8) {
            unsigned a[MT][4], b[NT][2];
#pragma unroll
            for (int mt = 0; mt < MT; mt++) {
                int r0 = wm + mt * 16 + gid;
                a[mt][0] = f2tf(As[s][r0][kk + tig]);
                a[mt][1] = f2tf(As[s][r0 + 8][kk + tig]);
                a[mt][2] = f2tf(As[s][r0][kk + tig + 4]);
                a[mt][3] = f2tf(As[s][r0 + 8][kk + tig + 4]);
            }
#pragma unroll
            for (int nt = 0; nt < NT; nt++) {
                int cn = wn + nt * 8 + gid;
                b[nt][0] = f2tf(Bs[s][kk + tig][cn]);
                b[nt][1] = f2tf(Bs[s][kk + tig + 4][cn]);
            }
#pragma unroll
            for (int mt = 0; mt < MT; mt++)
#pragma unroll
                for (int nt = 0; nt < NT; nt++)
                    mma_tf32(c[mt][nt], a[mt], b[nt]);
        }
    };

    issue(0, 0);
    for (int kt = 0; kt < KT; kt++) {
        if (kt + 1 < KT) { issue(kt + 1, (kt + 1) & 1); cpa_wait<1>(); }
        else             { cpa_wait<0>(); }
        __syncthreads();
        compute(kt & 1);
        __syncthreads();
    }

    // ---- epilogue: (+theta) bf16 store + f1/f2 ----
#pragma unroll
    for (int mt = 0; mt < MT; mt++) {
        int rl0 = wm + mt * 16 + gid;
        int rl1 = rl0 + 8;
        bool s0 = false, s1 = false;
        if (FUSE_THETA) {
            s0 = (obs[brow + rl0] == 1);
            s1 = (obs[brow + rl1] == 1);
        }
        float p10 = 0.f, p20 = 0.f, p11 = 0.f, p21 = 0.f;
#pragma unroll
        for (int nt = 0; nt < NT; nt++) {
            int col = wn + nt * 8 + tig * 2;
            float c0 = c[mt][nt][0], c1 = c[mt][nt][1];
            float c2 = c[mt][nt][2], c3 = c[mt][nt][3];
            if (FUSE_THETA) {
                float tw0 = g_tw[z * DD + col], tw1 = g_tw[z * DD + col + 1];
                if (s0) { c0 += tw0; c1 += tw1; }
                if (s1) { c2 += tw0; c3 += tw1; }
            }
            float a0 = __ldg(&avec[col]),      a1 = __ldg(&avec[col + 1]);
            float b0 = __ldg(&avec[Nc + col]), b1 = __ldg(&avec[Nc + col + 1]);
            p10 += c0 * a0 + c1 * a1;
            p20 += c0 * b0 + c1 * b1;
            p11 += c2 * a0 + c3 * a1;
            p21 += c2 * b0 + c3 * b1;
            *(__nv_bfloat162*)&Cb[(long)(brow + rl0) * Nc + col] =
                __float22bfloat162_rn(make_float2(c0, c1));
            *(__nv_bfloat162*)&Cb[(long)(brow + rl1) * Nc + col] =
                __float22bfloat162_rn(make_float2(c2, c3));
        }
#pragma unroll
        for (int o = 2; o; o >>= 1) {
            p10 += __shfl_down_sync(0xffffffffu, p10, o, 4);
            p20 += __shfl_down_sync(0xffffffffu, p20, o, 4);
            p11 += __shfl_down_sync(0xffffffffu, p11, o, 4);
            p21 += __shfl_down_sync(0xffffffffu, p21, o, 4);
        }
        if (tig == 0) {
            atomicAdd(&f1s[rl0], p10);
            atomicAdd(&f2s[rl0], p20);
            atomicAdd(&f1s[rl1], p11);
            atomicAdd(&f2s[rl1], p21);
        }
    }
    __syncthreads();
    if (tid < BM) {
        f1[brow + tid] = f1s[tid];
        f2[brow + tid] = f2s[tid];
    }
}

// ---------------- split-K output GEMM (fp32 partials, no atomics) ----------------
// grid = (SPLITK, M/64). Partial s writes g_who[s].
__global__ void mma_splitk(const float* __restrict__ A,
                           const float* __restrict__ B,
                           int M, int Nc, int K) {
    constexpr int BM = 64, BN = 64, BK = 16;
    constexpr int THREADS = 128;
    constexpr int MT = 2, NT = 4;        // WM=32, WN=32, warps 2x2
    constexpr int AP = BK + 4;
    constexpr int BP = BN + 8;
    constexpr int A_OPS = BM * BK / (4 * THREADS);
    constexpr int B_OPS = BK * BN / (4 * THREADS);

    __shared__ unsigned As[2][BM][AP];
    __shared__ unsigned Bs[2][BK][BP];

    int tid  = threadIdx.x;
    int ksp  = blockIdx.x;
    int brow = blockIdx.y * BM;
    int kBeg = ksp * (K / SPLITK);
    int warp = tid >> 5, lane = tid & 31;
    int gid  = lane >> 2, tig = lane & 3;
    int wm   = (warp / 2) * 32;
    int wn   = (warp % 2) * 32;
    float* Cf = g_who + (long)ksp * M * Nc;

    float c[MT][NT][4];
#pragma unroll
    for (int i = 0; i < MT; i++)
#pragma unroll
        for (int j = 0; j < NT; j++)
#pragma unroll
            for (int q = 0; q < 4; q++) c[i][j][q] = 0.0f;

    const int KT = (K / SPLITK) / BK;
    auto issue = [&](int kt, int s) {
        int k0 = kBeg + kt * BK;
#pragma unroll
        for (int l = 0; l < A_OPS; l++) {
            int idx = tid + l * THREADS;
            int r  = idx / (BK / 4);
            int c4 = idx % (BK / 4);
            cpa16(&As[s][r][c4 * 4], &A[(long)(brow + r) * K + k0 + c4 * 4]);
        }
#pragma unroll
        for (int l = 0; l < B_OPS; l++) {
            int idx = tid + l * THREADS;
            int r  = idx / (BN / 4);
            int c4 = idx % (BN / 4);
            cpa16(&Bs[s][r][c4 * 4], &B[(long)(k0 + r) * Nc + c4 * 4]);
        }
        cpa_commit();
    };
    auto compute = [&](int s) {
#pragma unroll
        for (int kk = 0; kk < BK; kk += 8) {
            unsigned a[MT][4], b[NT][2];
#pragma unroll
            for (int mt = 0; mt < MT; mt++) {
                int r0 = wm + mt * 16 + gid;
                a[mt][0] = f2tf(As[s][r0][kk + tig]);
                a[mt][1] = f2tf(As[s][r0 + 8][kk + tig]);
                a[mt][2] = f2tf(As[s][r0][kk + tig + 4]);
                a[mt][3] = f2tf(As[s][r0 + 8][kk + tig + 4]);
            }
#pragma unroll
            for (int nt = 0; nt < NT; nt++) {
                int cn = wn + nt * 8 + gid;
                b[nt][0] = f2tf(Bs[s][kk + tig][cn]);
                b[nt][1] = f2tf(Bs[s][kk + tig + 4][cn]);
            }
#pragma unroll
            for (int mt = 0; mt < MT; mt++)
#pragma unroll
                for (int nt = 0; nt < NT; nt++)
                    mma_tf32(c[mt][nt], a[mt], b[nt]);
        }
    };

    issue(0, 0);
    for (int kt = 0; kt < KT; kt++) {
        if (kt + 1 < KT) { issue(kt + 1, (kt + 1) & 1); cpa_wait<1>(); }
        else             { cpa_wait<0>(); }
        __syncthreads();
        compute(kt & 1);
        __syncthreads();
    }

#pragma unroll
    for (int mt = 0; mt < MT; mt++) {
        int rl0 = brow + wm + mt * 16 + gid;
        int rl1 = rl0 + 8;
#pragma unroll
        for (int nt = 0; nt < NT; nt++) {
            int col = wn + nt * 8 + tig * 2;
            *(float2*)&Cf[(long)rl0 * Nc + col] = make_float2(c[mt][nt][0], c[mt][nt][1]);
            *(float2*)&Cf[(long)rl1 * Nc + col] = make_float2(c[mt][nt][2], c[mt][nt][3]);
        }
    }
}

// ---------------- combine split-K partials + f1o/f2o + bf16 ----------------
__global__ void out_epi(const float* __restrict__ ao) {
    int warp = threadIdx.x >> 5, lane = threadIdx.x & 31;
    int r = blockIdx.x * 8 + warp;
    float v0 = 0.f, v1 = 0.f;
#pragma unroll
    for (int s = 0; s < SPLITK; s++) {
        const float* row = g_who + (long)s * NN * OUTD + (long)r * OUTD;
        v0 += row[lane];
        v1 += row[lane + 32];
    }
    float p1 = v0 * __ldg(&ao[lane]) + v1 * __ldg(&ao[lane + 32]);
    float p2 = v0 * __ldg(&ao[OUTD + lane]) + v1 * __ldg(&ao[OUTD + lane + 32]);
#pragma unroll
    for (int o = 16; o; o >>= 1) {
        p1 += __shfl_xor_sync(0xffffffffu, p1, o);
        p2 += __shfl_xor_sync(0xffffffffu, p2, o);
    }
    if (lane == 0) { g_f1o[r] = p1; g_f2o[r] = p2; }
    g_Whob[r * OUTD + lane]      = __float2bfloat16(v0);
    g_Whob[r * OUTD + lane + 32] = __float2bfloat16(v1);
}

// ---------------- bf16x2 -> 2 floats (exact) ----------------
__device__ __forceinline__ float2 bf2f(unsigned u) {
    float2 r;
    r.x = __int_as_float(u << 16);
    r.y = __int_as_float(u & 0xffff0000u);
    return r;
}

// ---------------- warp-per-(i,h) sparse attention + ELU ----------------
// block = 256 (8 warps), grid = (NN/8, nHeads).
template <int D>
__global__ void attn_warp(const __nv_bfloat16* __restrict__ Whb,
                          const float* __restrict__ f1,
                          const float* __restrict__ f2,
                          float* __restrict__ out,
                          int iStride, int hStride) {
    constexpr int WPB = 8;
    constexpr int FPL = D / 32;
    __shared__ __align__(16) float2 wns[WPB][MAXD];
    int warp = threadIdx.x >> 5, lane = threadIdx.x & 31;
    int i = blockIdx.x * WPB + warp;
    int h = blockIdx.y;
    const __nv_bfloat16* WhH = Whb + h * (NN * D);
    const float* f2H = f2 + h * NN;
    float f1i = f1[h * NN + i];
    int d = g_deg[i];
    float2* w = wns[warp];
    const unsigned FULL = 0xffffffffu;

    float m = -3.4e38f;
    for (int k = lane; k < d; k += 32) {
        int j = g_nbr[i * MAXD + k];
        float e = f1i + f2H[j];
        e = (e > 0.0f) ? e : 0.2f * e;
        m = fmaxf(m, e);
        w[k] = make_float2(e, __int_as_float(j * (D * 2)));
    }
#pragma unroll
    for (int o = 16; o; o >>= 1) m = fmaxf(m, __shfl_xor_sync(FULL, m, o));

    float s = 0.0f;
    for (int k = lane; k < d; k += 32) {
        float v = __expf(w[k].x - m);
        w[k].x = v;
        s += v;
    }
#pragma unroll
    for (int o = 16; o; o >>= 1) s += __shfl_xor_sync(FULL, s, o);
    __syncwarp();

    const char* basep = (const char*)WhH + lane * (FPL * 2);
    float acc[FPL];
#pragma unroll
    for (int q = 0; q < FPL; q++) acc[q] = 0.0f;

    if (d > 0) {
#pragma unroll 8
        for (int k = 0; k < d; k++) {
            float2 p = w[k];
            float wk = p.x;
            int off = __float_as_int(p.y);
            if (FPL == 4) {
                uint2 raw = *(const uint2*)(basep + off);
                float2 c0 = bf2f(raw.x);
                float2 c1 = bf2f(raw.y);
                acc[0] += wk * c0.x; acc[1] += wk * c0.y;
                acc[2] += wk * c1.x; acc[3] += wk * c1.y;
            } else {
                unsigned raw = *(const unsigned*)(basep + off);
                float2 c0 = bf2f(raw);
                acc[0] += wk * c0.x; acc[1] += wk * c0.y;
            }
        }
        float inv = 1.0f / s;
#pragma unroll
        for (int q = 0; q < FPL; q++) acc[q] *= inv;
    } else {
        for (int k = 0; k < NN; k++) {
            if (FPL == 4) {
                uint2 raw = *(const uint2*)(basep + k * (D * 2));
                float2 c0 = bf2f(raw.x);
                float2 c1 = bf2f(raw.y);
                acc[0] += c0.x; acc[1] += c0.y; acc[2] += c1.x; acc[3] += c1.y;
            } else {
                unsigned raw = *(const unsigned*)(basep + k * (D * 2));
                float2 c0 = bf2f(raw);
                acc[0] += c0.x; acc[1] += c0.y;
            }
        }
#pragma unroll
        for (int q = 0; q < FPL; q++) acc[q] *= (1.0f / NN);
    }

    float* op = out + (long)i * iStride + h * hStride + lane * FPL;
#pragma unroll
    for (int q = 0; q < FPL; q++) acc[q] = (acc[q] > 0.0f) ? acc[q] : expm1f(acc[q]);
    if (FPL == 4) *(float4*)op = make_float4(acc[0], acc[1], acc[2], acc[3]);
    else          *(float2*)op = make_float2(acc[0], acc[1]);
}

// ---------------- launch ----------------
extern "C" void kernel_launch(void* const* d_in, const int* in_sizes, int n_in,
                              void* d_out, int out_size) {
    const float* x     = (const float*)d_in[0];
    const float* adj   = (const float*)d_in[1];
    const int*   obs   = (const int*)  d_in[2];
    // d_in[3] = s_mat (unused)
    const float* theta = (const float*)d_in[4];
    const float* W0    = (const float*)d_in[5];
    const float* a0    = (const float*)d_in[6];
    const float* W1    = (const float*)d_in[7];
    const float* a1    = (const float*)d_in[8];
    const float* Wo    = (const float*)d_in[9];
    const float* ao    = (const float*)d_in[10];
    float* out = (float*)d_out;

    void *pWhb, *pHa, *pHc, *pWhob, *pF1, *pF2, *pF1o, *pF2o;
    cudaGetSymbolAddress(&pWhb,  g_Whb);
    cudaGetSymbolAddress(&pHa,   g_ha);
    cudaGetSymbolAddress(&pHc,   g_hc);
    cudaGetSymbolAddress(&pWhob, g_Whob);
    cudaGetSymbolAddress(&pF1,   g_f1);
    cudaGetSymbolAddress(&pF2,   g_f2);
    cudaGetSymbolAddress(&pF1o,  g_f1o);
    cudaGetSymbolAddress(&pF2o,  g_f2o);

    thetaW_kernel<<<HH, DD>>>(theta, W0);
    build_csr_kernel<<<NN, 256>>>(adj);

    // ---- layer 0 (theta merged in epilogue) ----
    mma_gemm<64, 128, 16, 32, 64, true><<<dim3(1, NN / 64, HH), 128>>>(
        x, W0, (__nv_bfloat16*)pWhb, a0,
        (float*)pF1, (float*)pF2, NN, DD, FF,
        0L, (long)FF * DD, 2L * DD, obs);
    attn_warp<DD><<<dim3(NN / 8, HH), 256>>>((const __nv_bfloat16*)pWhb,
                                             (const float*)pF1, (const float*)pF2,
                                             (float*)pHa, DD, NN * DD);

    // ---- layer 1 (output written directly in concat layout) ----
    mma_gemm<64, 128, 16, 32, 64, false><<<dim3(1, NN / 64, HH), 128>>>(
        (const float*)pHa, W1, (__nv_bfloat16*)pWhb, a1,
        (float*)pF1, (float*)pF2, NN, DD, DD,
        (long)NN * DD, (long)DD * DD, 2L * DD, nullptr);
    attn_warp<DD><<<dim3(NN / 8, HH), 256>>>((const __nv_bfloat16*)pWhb,
                                             (const float*)pF1, (const float*)pF2,
                                             (float*)pHc, HH * DD, DD);

    // ---- output layer: split-K GEMM + combine ----
    mma_splitk<<<dim3(SPLITK, NN / 64), 128>>>(
        (const float*)pHc, Wo, NN, OUTD, HH * DD);
    out_epi<<<NN / 8, 256>>>(ao);
    attn_warp<OUTD><<<dim3(NN / 8, 1), 256>>>((const __nv_bfloat16*)pWhob,
                                              (const float*)pF1o, (const float*)pF2o,
                                              out, OUTD, 0);
    (void)in_sizes; (void)n_in; (void)out_size;
}